// round 16
// baseline (speedup 1.0000x reference)
#include <cuda_runtime.h>
#include <math.h>
#include <cstdint>

#define BB 4
#define QQ 256
#define CCN 1024
#define QDIM 512
#define CDIM 512
#define HH 128

// ---------------- fp32 scratch ----------------
__device__ float g_Ec[BB * CCN * HH];
__device__ float g_Eq[BB * QQ * HH];
__device__ float g_qpart[BB * QQ * QDIM];
__device__ float g_attn_scratch[BB * QQ * CCN];

// ---------------- fragment-blocked bf16 hi/lo scratch (u32) ----------------
__device__ uint32_t g_ctxAh[1048576], g_ctxAl[1048576];   // ctx as A: 256mt x 32kt
__device__ uint32_t g_qryAh[262144],  g_qryAl[262144];    // query as A: 64 x 32
__device__ uint32_t g_ctxBh[1048576], g_ctxBl[1048576];   // ctx as B: 4b x 64ntb x 64kt
__device__ uint32_t g_wcwBh[32768],   g_wcwBl[32768];     // wc_w as B: 16 x 32
__device__ uint32_t g_wqwBh[32768],   g_wqwBl[32768];     // wq_w as B: 16 x 32
__device__ uint32_t g_lo1Bh[131072],  g_lo1Bl[131072];    // lo_w[:, :512] as B: 64 x 32
__device__ uint32_t g_lo2Bh[131072],  g_lo2Bl[131072];    // lo_w[:, 512:] as B: 64 x 32
__device__ uint32_t g_attnAh[524288], g_attnAl[524288];   // attn as A: 64 x 64
__device__ uint32_t g_wcAh[262144],   g_wcAl[262144];     // wc as A: 64 x 32

#define TWO_LOG2E 2.8853900817779268f

__device__ __forceinline__ float fast_ex2(float x) {
    float e; asm("ex2.approx.f32 %0, %1;" : "=f"(e) : "f"(x)); return e;
}
__device__ __forceinline__ float fast_rcp(float x) {
    float r; asm("rcp.approx.f32 %0, %1;" : "=f"(r) : "f"(x)); return r;
}
__device__ __forceinline__ float fast_tanh(float x) {
    float e = fast_ex2(x * TWO_LOG2E);
    return fmaf(-2.0f, fast_rcp(e + 1.0f), 1.0f);
}

// ---------------- bf16 split helpers (validated R13/R14) ----------------
__device__ __forceinline__ uint32_t pack_hi(float e0, float e1) {
    uint32_t r;
    asm("prmt.b32 %0, %1, %2, 0x7632;" : "=r"(r)
        : "r"(__float_as_uint(e0)), "r"(__float_as_uint(e1)));
    return r;
}
__device__ __forceinline__ uint32_t pack_lo(float e0, float e1) {
    float h0 = __uint_as_float(__float_as_uint(e0) & 0xFFFF0000u);
    float h1 = __uint_as_float(__float_as_uint(e1) & 0xFFFF0000u);
    uint32_t r;
    asm("cvt.rn.bf16x2.f32 %0, %1, %2;" : "=r"(r) : "f"(e1 - h1), "f"(e0 - h0));
    return r;
}

__device__ __forceinline__ void mma_bf16(float* c, const uint32_t* a, const uint32_t* b) {
    asm volatile(
        "mma.sync.aligned.m16n8k16.row.col.f32.bf16.bf16.f32 "
        "{%0,%1,%2,%3}, {%4,%5,%6,%7}, {%8,%9}, {%0,%1,%2,%3};"
        : "+f"(c[0]), "+f"(c[1]), "+f"(c[2]), "+f"(c[3])
        : "r"(a[0]), "r"(a[1]), "r"(a[2]), "r"(a[3]), "r"(b[0]), "r"(b[1]));
}

// ---------------- conversion warp-tasks (validated R14) ----------------
__device__ __forceinline__ void conv_A(const float* __restrict__ X, int ld,
                                       int mt, int kt, int nkt,
                                       uint32_t* __restrict__ Ah,
                                       uint32_t* __restrict__ Al, int lane)
{
    const int g = lane >> 2, t4 = lane & 3;
    uint4 h, l;
    uint32_t* ph = &h.x; uint32_t* pl = &l.x;
#pragma unroll
    for (int j = 0; j < 4; j++) {
        const int r = mt * 16 + g + 8 * (j & 1);
        const int k = kt * 16 + t4 * 2 + 8 * (j >> 1);
        float2 v = *(const float2*)&X[(long)r * ld + k];
        ph[j] = pack_hi(v.x, v.y);
        pl[j] = pack_lo(v.x, v.y);
    }
    const long base = ((long)mt * nkt + kt) * 128 + lane * 4;
    *(uint4*)&Ah[base] = h;
    *(uint4*)&Al[base] = l;
}

__device__ __forceinline__ void conv_B_rm(const float* __restrict__ X, int ld,
                                          int ntb, int kt, int nkt,
                                          uint32_t* __restrict__ Bh,
                                          uint32_t* __restrict__ Bl, int lane)
{
    const int n = ntb * 8 + (lane >> 2), t4 = lane & 3;
    uint2 h, l;
#pragma unroll
    for (int j = 0; j < 2; j++) {
        const int k = kt * 16 + t4 * 2 + 8 * j;
        float2 v = *(const float2*)&X[(long)n * ld + k];
        (&h.x)[j] = pack_hi(v.x, v.y);
        (&l.x)[j] = pack_lo(v.x, v.y);
    }
    const long base = ((long)ntb * nkt + kt) * 64 + lane * 2;
    *(uint2*)&Bh[base] = h;
    *(uint2*)&Bl[base] = l;
}

__device__ __forceinline__ void conv_B_tr(const float* __restrict__ X, int ld,
                                          int ntb, int kt, int nkt,
                                          uint32_t* __restrict__ Bh,
                                          uint32_t* __restrict__ Bl, int lane)
{
    const int n = ntb * 8 + (lane >> 2), t4 = lane & 3;
    uint2 h, l;
#pragma unroll
    for (int j = 0; j < 2; j++) {
        const int k = kt * 16 + t4 * 2 + 8 * j;
        float x0 = X[(long)k * ld + n];
        float x1 = X[(long)(k + 1) * ld + n];
        (&h.x)[j] = pack_hi(x0, x1);
        (&l.x)[j] = pack_lo(x0, x1);
    }
    const long base = ((long)ntb * nkt + kt) * 64 + lane * 2;
    *(uint2*)&Bh[base] = h;
    *(uint2*)&Bl[base] = l;
}

// ---------------- input conversion kernel (7936 CTAs x 128) ----------------
__global__ __launch_bounds__(128)
void conv_inputs_kernel(const float* __restrict__ context,
                        const float* __restrict__ query,
                        const float* __restrict__ wc_w,
                        const float* __restrict__ wq_w,
                        const float* __restrict__ lo_w)
{
    const int task = blockIdx.x * 4 + (threadIdx.x >> 5);
    const int lane = threadIdx.x & 31;

    if (task < 8192) {
        conv_A(context, CDIM, task >> 5, task & 31, 32, g_ctxAh, g_ctxAl, lane);
    } else if (task < 10240) {
        const int t = task - 8192;
        conv_A(query, QDIM, t >> 5, t & 31, 32, g_qryAh, g_qryAl, lane);
    } else if (task < 26624) {
        const int t = task - 10240;
        const int b = t >> 12, rem = t & 4095;
        conv_B_tr(context + (long)b * CCN * CDIM, CDIM, rem >> 6, rem & 63, 64,
                  g_ctxBh + (long)b * 262144, g_ctxBl + (long)b * 262144, lane);
    } else if (task < 27136) {
        const int t = task - 26624;
        conv_B_rm(wc_w, CDIM, t >> 5, t & 31, 32, g_wcwBh, g_wcwBl, lane);
    } else if (task < 27648) {
        const int t = task - 27136;
        conv_B_rm(wq_w, QDIM, t >> 5, t & 31, 32, g_wqwBh, g_wqwBl, lane);
    } else if (task < 29696) {
        const int t = task - 27648;
        conv_B_rm(lo_w, QDIM + CDIM, t >> 5, t & 31, 32, g_lo1Bh, g_lo1Bl, lane);
    } else {
        const int t = task - 29696;
        conv_B_rm(lo_w + CDIM, QDIM + CDIM, t >> 5, t & 31, 32, g_lo2Bh, g_lo2Bl, lane);
    }
}

// ---------------- attn conversion kernel (1024 CTAs x 128) -----------------
__global__ __launch_bounds__(128)
void conv_attn_kernel(const float* __restrict__ attn)
{
    const int task = blockIdx.x * 4 + (threadIdx.x >> 5);
    const int lane = threadIdx.x & 31;
    conv_A(attn, CCN, task >> 6, task & 63, 64, g_attnAh, g_attnAl, lane);
}

// ---------------- frag-staged tensor-core GEMM: 32x64 tile, 128 thr --------
// Warp w: mtile wm=w&1 (16 rows), ntiles 4*(w>>1)..4*(w>>1)+3 (32 cols).
// Per chunk per warp: 12 MMA + 10 LDS. Staging: A 1 uint4/thr, B 2 uint4/thr.
__device__ __forceinline__
void gemm_fs(const uint32_t* __restrict__ Ah, const uint32_t* __restrict__ Al,
             int a_mt0, int a_nkt,
             const uint32_t* __restrict__ Bh, const uint32_t* __restrict__ Bl,
             int b_nt0, int b_nkt,
             const float* __restrict__ bias, const float* __restrict__ Add,
             float* __restrict__ C, int ldc, int m_base, int n0,
             int NKT, int epi,
             uint32_t* __restrict__ FAh, uint32_t* __restrict__ FAl,
             int f_mt0, int f_nkt)
{
    __shared__ uint32_t As[1024];   // [buf2][split2][mtile2][128]
    __shared__ uint32_t Bs[2048];   // [buf2][split2][ntile8][64]

    const int tid  = threadIdx.x;
    const int lane = tid & 31;
    const int wid  = tid >> 5;       // 0..3
    const int wm   = wid & 1;        // mtile
    const int wn   = wid >> 1;       // 0..1 -> ntiles 4wn..4wn+3

    // staging: A one uint4 per thread
    const int gA = tid >> 5, spA = gA >> 1, mtA = gA & 1;
    const int ixA = (tid & 31) * 4;
    // staging: B two uint4 per thread (split 0 and 1)
    const int ntB = tid >> 4;        // 0..7
    const int ixB = (tid & 15) * 4;

    const uint32_t* srcA  = (spA ? Al : Ah) + ((long)(a_mt0 + mtA) * a_nkt) * 128 + ixA;
    const uint32_t* srcB0 = Bh + ((long)(b_nt0 + ntB) * b_nkt) * 64 + ixB;
    const uint32_t* srcB1 = Bl + ((long)(b_nt0 + ntB) * b_nkt) * 64 + ixB;
    uint32_t* const dstA  = &As[(spA * 2 + mtA) * 128 + ixA];
    uint32_t* const dstB0 = &Bs[ntB * 64 + ixB];
    uint32_t* const dstB1 = &Bs[512 + ntB * 64 + ixB];

    float acc[4][4];                 // ntloc 0..3
#pragma unroll
    for (int nt = 0; nt < 4; nt++)
#pragma unroll
        for (int i = 0; i < 4; i++) acc[nt][i] = 0.f;

    uint4 ra  = *(const uint4*)(srcA);
    uint4 rb0 = *(const uint4*)(srcB0);
    uint4 rb1 = *(const uint4*)(srcB1);
    *(uint4*)dstA  = ra;
    *(uint4*)dstB0 = rb0;
    *(uint4*)dstB1 = rb1;
    if (1 < NKT) {
        ra  = *(const uint4*)(srcA + 128);
        rb0 = *(const uint4*)(srcB0 + 64);
        rb1 = *(const uint4*)(srcB1 + 64);
    }
    __syncthreads();

    int cur = 0;
    for (int kt = 0; kt < NKT; kt++) {
        uint32_t ah[4], al[4], bh[4][2], bl[4][2];
        *(uint4*)ah = *(const uint4*)&As[((cur * 2 + 0) * 2 + wm) * 128 + lane * 4];
        *(uint4*)al = *(const uint4*)&As[((cur * 2 + 1) * 2 + wm) * 128 + lane * 4];
#pragma unroll
        for (int nt = 0; nt < 4; nt++) {
            const int ntile = wn * 4 + nt;
            *(uint2*)bh[nt] = *(const uint2*)&Bs[((cur * 2 + 0) * 8 + ntile) * 64 + lane * 2];
            *(uint2*)bl[nt] = *(const uint2*)&Bs[((cur * 2 + 1) * 8 + ntile) * 64 + lane * 2];
        }
#pragma unroll
        for (int nt = 0; nt < 4; nt++) {
            mma_bf16(acc[nt], ah, bh[nt]);
            mma_bf16(acc[nt], ah, bl[nt]);
            mma_bf16(acc[nt], al, bh[nt]);
        }

        if (kt + 1 < NKT) {
            *(uint4*)(dstA + (cur ^ 1) * 512)   = ra;
            *(uint4*)(dstB0 + (cur ^ 1) * 1024) = rb0;
            *(uint4*)(dstB1 + (cur ^ 1) * 1024) = rb1;
        }
        if (kt + 2 < NKT) {
            ra  = *(const uint4*)(srcA + (long)(kt + 2) * 128);
            rb0 = *(const uint4*)(srcB0 + (long)(kt + 2) * 64);
            rb1 = *(const uint4*)(srcB1 + (long)(kt + 2) * 64);
        }
        __syncthreads();
        cur ^= 1;
    }

    if (FAh) {
        // write C as A-frag hi/lo: warp covers 2 ktg blocks (nt pairs)
        const int mtg = f_mt0 + wm;
#pragma unroll
        for (int p = 0; p < 2; p++) {
            const int ktg = ((n0 + wn * 32) >> 4) + p;
            uint4 h, l;
            h.x = pack_hi(acc[2 * p][0], acc[2 * p][1]);
            l.x = pack_lo(acc[2 * p][0], acc[2 * p][1]);
            h.y = pack_hi(acc[2 * p][2], acc[2 * p][3]);
            l.y = pack_lo(acc[2 * p][2], acc[2 * p][3]);
            h.z = pack_hi(acc[2 * p + 1][0], acc[2 * p + 1][1]);
            l.z = pack_lo(acc[2 * p + 1][0], acc[2 * p + 1][1]);
            h.w = pack_hi(acc[2 * p + 1][2], acc[2 * p + 1][3]);
            l.w = pack_lo(acc[2 * p + 1][2], acc[2 * p + 1][3]);
            const long base = ((long)mtg * f_nkt + ktg) * 128 + lane * 4;
            *(uint4*)&FAh[base] = h;
            *(uint4*)&FAl[base] = l;
        }
        return;
    }

    const int g   = lane >> 2;
    const int tig = lane & 3;
#pragma unroll
    for (int nt = 0; nt < 4; nt++) {
        const int col = n0 + wn * 32 + nt * 8 + tig * 2;
        float2 b2 = bias ? *(const float2*)&bias[col] : make_float2(0.f, 0.f);
#pragma unroll
        for (int half = 0; half < 2; half++) {
            const int row = m_base + wm * 16 + g + half * 8;
            float v0 = acc[nt][half * 2 + 0] + b2.x;
            float v1 = acc[nt][half * 2 + 1] + b2.y;
            if (Add) {
                float2 a2 = *(const float2*)&Add[(long)row * ldc + col];
                v0 += a2.x; v1 += a2.y;
            }
            if (epi == 1) {
                v0 = fast_ex2(v0 * TWO_LOG2E); v1 = fast_ex2(v1 * TWO_LOG2E);
            } else if (epi == 2) {
                v0 = fast_tanh(v0); v1 = fast_tanh(v1);
            }
            *(float2*)&C[(long)row * ldc + col] = make_float2(v0, v1);
        }
    }
}

// ---------------- fused projections: Ec, Eq, qpart (576 CTAs) --------------
__global__ __launch_bounds__(128)
void proj_fused_kernel(const float* __restrict__ wc_b,
                       const float* __restrict__ wq_b,
                       const float* __restrict__ lo_b,
                       float* __restrict__ Ec, float* __restrict__ Eq,
                       float* __restrict__ qpart)
{
    const int i = blockIdx.x;
    if (i < 256) {               // Ec: 128 m-tiles(32) x 2 n-tiles(64)
        const int m0 = (i >> 1) * 32, n0 = (i & 1) * 64;
        gemm_fs(g_ctxAh, g_ctxAl, m0 >> 4, 32,
                g_wcwBh, g_wcwBl, n0 >> 3, 32,
                wc_b, nullptr, Ec, HH, m0, n0, 32, 1,
                nullptr, nullptr, 0, 0);
    } else if (i < 320) {        // Eq: 32 x 2
        const int j = i - 256;
        const int m0 = (j >> 1) * 32, n0 = (j & 1) * 64;
        gemm_fs(g_qryAh, g_qryAl, m0 >> 4, 32,
                g_wqwBh, g_wqwBl, n0 >> 3, 32,
                wq_b, nullptr, Eq, HH, m0, n0, 32, 1,
                nullptr, nullptr, 0, 0);
    } else {                     // qpart: 32 x 8
        const int j = i - 320;
        const int m0 = (j >> 3) * 32, n0 = (j & 7) * 64;
        gemm_fs(g_qryAh, g_qryAl, m0 >> 4, 32,
                g_lo2Bh, g_lo2Bl, n0 >> 3, 32,
                lo_b, nullptr, qpart, QDIM, m0, n0, 32, 0,
                nullptr, nullptr, 0, 0);
    }
}

// ---------------- wc = attn @ context -> frag out (256 CTAs) ---------------
__global__ __launch_bounds__(128)
void gemm_nn_kernel()
{
    const int b  = blockIdx.z;
    const int m0 = blockIdx.y * 32;
    const int n0 = blockIdx.x * 64;
    const int mt0 = (b * QQ + m0) >> 4;
    gemm_fs(g_attnAh, g_attnAl, mt0, 64,
            g_ctxBh + (long)b * 262144, g_ctxBl + (long)b * 262144, n0 >> 3, 64,
            nullptr, nullptr, nullptr, 0, 0, n0, 64, 0,
            g_wcAh, g_wcAl, mt0, 32);
}

// ---------------- out = tanh(wc @ lo_w[:,:512].T + qpart) (256 CTAs) -------
__global__ __launch_bounds__(128)
void gemm_out_kernel(const float* __restrict__ qpart, float* __restrict__ out)
{
    const int m0 = blockIdx.y * 32, n0 = blockIdx.x * 64;
    gemm_fs(g_wcAh, g_wcAl, m0 >> 4, 32,
            g_lo1Bh, g_lo1Bl, n0 >> 3, 32,
            nullptr, qpart, out, QDIM, m0, n0, 32, 2,
            nullptr, nullptr, 0, 0);
}

// ---------------- emission + masked softmax: paired reciprocals ------------
#define QT 4
#define CH 32
#define NCHUNK (CCN / CH)
#define ECPAD 132

__global__ __launch_bounds__(128)
void emission_softmax2(const float* __restrict__ Ec,
                       const float* __restrict__ Eq,
                       const int* __restrict__ mask,
                       const float* __restrict__ we_w,
                       const float* __restrict__ we_b,
                       float* __restrict__ attn)
{
    __shared__ float ecs[CH][ECPAD];
    __shared__ float eqs[QT][HH];
    __shared__ float wes[HH];
    __shared__ int ms[CH];

    const int b  = blockIdx.y;
    const int q0 = blockIdx.x * QT;
    const int tid = threadIdx.x;
    const int lane = tid & 31;
    const int q = tid >> 5;

    if (tid < HH) wes[tid] = we_w[tid];
    {
        const float4* src = (const float4*)&Eq[(long)(b * QQ + q0) * HH];
        float4* dst = (float4*)&eqs[0][0];
        for (int i = tid; i < QT * HH / 4; i += 128) dst[i] = src[i];
    }
    __syncthreads();

    float W = 0.f;
#pragma unroll
    for (int h = 0; h < HH; h += 4) {
        float4 w4 = *(const float4*)&wes[h];
        W += (w4.x + w4.y) + (w4.z + w4.w);
    }
    const float eb = we_b[0];

    float es_l[NCHUNK];

    for (int ch = 0; ch < NCHUNK; ch++) {
        __syncthreads();
        {
            const float4* src = (const float4*)&Ec[((long)b * CCN + ch * CH) * HH];
            for (int i = tid; i < CH * HH / 4; i += 128) {
                int r  = i >> 5;
                int c4 = (i & 31) * 4;
                *(float4*)&ecs[r][c4] = src[i];
            }
            if (tid < CH) ms[tid] = mask[b * CCN + ch * CH + tid];
        }
        __syncthreads();

        float s0 = 0.f, s1 = 0.f;
#pragma unroll
        for (int h = 0; h < HH; h += 8) {
            float4 e0 = *(const float4*)&ecs[lane][h];
            float4 g0 = *(const float4*)&eqs[q][h];
            float4 w0 = *(const float4*)&wes[h];
            float4 e1 = *(const float4*)&ecs[lane][h + 4];
            float4 g1 = *(const float4*)&eqs[q][h + 4];
            float4 w1 = *(const float4*)&wes[h + 4];

            {
                float A0 = fmaf(e0.x, g0.x, 1.f), A1 = fmaf(e0.y, g0.y, 1.f);
                float num = fmaf(w0.x, A1, w0.y * A0);
                s0 = fmaf(num, fast_rcp(A0 * A1), s0);
            }
            {
                float A0 = fmaf(e0.z, g0.z, 1.f), A1 = fmaf(e0.w, g0.w, 1.f);
                float num = fmaf(w0.z, A1, w0.w * A0);
                s1 = fmaf(num, fast_rcp(A0 * A1), s1);
            }
            {
                float A0 = fmaf(e1.x, g1.x, 1.f), A1 = fmaf(e1.y, g1.y, 1.f);
                float num = fmaf(w1.x, A1, w1.y * A0);
                s0 = fmaf(num, fast_rcp(A0 * A1), s0);
            }
            {
                float A0 = fmaf(e1.z, g1.z, 1.f), A1 = fmaf(e1.w, g1.w, 1.f);
                float num = fmaf(w1.z, A1, w1.w * A0);
                s1 = fmaf(num, fast_rcp(A0 * A1), s1);
            }
        }
        float s = s0 + s1;
        es_l[ch] = ms[lane] ? (fmaf(-2.f, s, W) + eb) : -INFINITY;
    }

    float lm = -INFINITY;
#pragma unroll
    for (int ch = 0; ch < NCHUNK; ch++) lm = fmaxf(lm, es_l[ch]);
#pragma unroll
    for (int off = 16; off >= 1; off >>= 1)
        lm = fmaxf(lm, __shfl_xor_sync(0xffffffffu, lm, off));
    const bool ok = (lm > -3.0e38f);

    float ls = 0.f;
#pragma unroll
    for (int ch = 0; ch < NCHUNK; ch++) {
        float e = ok ? __expf(es_l[ch] - lm) : 0.f;
        es_l[ch] = e;
        ls += e;
    }
#pragma unroll
    for (int off = 16; off >= 1; off >>= 1)
        ls += __shfl_xor_sync(0xffffffffu, ls, off);
    const float inv = (ls > 0.f) ? 1.f / ls : 0.f;

    float* arow = attn + (long)(b * QQ + q0 + q) * CCN;
#pragma unroll
    for (int ch = 0; ch < NCHUNK; ch++) arow[ch * CH + lane] = es_l[ch] * inv;
}

// ---------------- launcher: serial single-stream (graph-safe) --------------
extern "C" void kernel_launch(void* const* d_in, const int* in_sizes, int n_in,
                              void* d_out, int out_size)
{
    const float* query   = (const float*)d_in[0];
    const float* context = (const float*)d_in[1];
    const int*   mask    = (const int*)d_in[2];
    const float* wq_w = (const float*)d_in[3];
    const float* wq_b = (const float*)d_in[4];
    const float* wc_w = (const float*)d_in[5];
    const float* wc_b = (const float*)d_in[6];
    const float* we_w = (const float*)d_in[7];
    const float* we_b = (const float*)d_in[8];
    const float* lo_w = (const float*)d_in[9];
    const float* lo_b = (const float*)d_in[10];

    float *Ec, *Eq, *qpart, *attn_s;
    cudaGetSymbolAddress((void**)&Ec, g_Ec);
    cudaGetSymbolAddress((void**)&Eq, g_Eq);
    cudaGetSymbolAddress((void**)&qpart, g_qpart);
    cudaGetSymbolAddress((void**)&attn_s, g_attn_scratch);

    const int nOut  = BB * QQ * QDIM;
    const int nAttn = BB * QQ * CCN;
    float* outPtr  = nullptr;
    float* attnPtr = nullptr;
    if (out_size >= nOut + nAttn) {
        outPtr  = (float*)d_out;
        attnPtr = (float*)d_out + nOut;
    } else if (out_size == nAttn) {
        attnPtr = (float*)d_out;
    } else {
        outPtr = (float*)d_out;
    }
    if (!attnPtr) attnPtr = attn_s;

    // 1) convert all GEMM inputs to fragment-blocked bf16 hi/lo
    conv_inputs_kernel<<<7936, 128>>>(context, query, wc_w, wq_w, lo_w);

    // 2) Ec, Eq, qpart (tensor cores, 576 CTAs)
    proj_fused_kernel<<<576, 128>>>(wc_b, wq_b, lo_b, Ec, Eq, qpart);

    // 3) emission + softmax -> attn (256 CTAs)
    emission_softmax2<<<dim3(QQ / QT, BB), 128>>>(Ec, Eq, mask, we_w, we_b, attnPtr);

    if (outPtr) {
        // 4) attn -> frag layout (1024 CTAs)
        conv_attn_kernel<<<1024, 128>>>(attnPtr);

        // 5) wc = attn @ context, written directly as A-frags (256 CTAs)
        gemm_nn_kernel<<<dim3(CDIM / 64, QQ / 32, BB), 128>>>();

        // 6) out = tanh(wc @ lo_w[:,:512].T + qpart) (256 CTAs)
        gemm_out_kernel<<<dim3(QDIM / 64, BB * QQ / 32), 128>>>(qpart, outPtr);
    }
}

// round 17
// speedup vs baseline: 1.0330x; 1.0330x over previous
#include <cuda_runtime.h>
#include <math.h>
#include <cstdint>

#define BB 4
#define QQ 256
#define CCN 1024
#define QDIM 512
#define CDIM 512
#define HH 128

// ---------------- fp32 scratch ----------------
__device__ float g_Ec[BB * CCN * HH];
__device__ float g_Eq[BB * QQ * HH];
__device__ float g_qpart[BB * QQ * QDIM];
__device__ float g_attn_scratch[BB * QQ * CCN];

// ---------------- fragment-blocked bf16 hi/lo scratch (u32) ----------------
__device__ uint32_t g_ctxAh[1048576], g_ctxAl[1048576];   // ctx as A: 256mt x 32kt
__device__ uint32_t g_qryAh[262144],  g_qryAl[262144];    // query as A: 64 x 32
__device__ uint32_t g_ctxBh[1048576], g_ctxBl[1048576];   // ctx as B: 4b x 64ntb x 64kt
__device__ uint32_t g_wcwBh[32768],   g_wcwBl[32768];     // wc_w as B: 16 x 32
__device__ uint32_t g_wqwBh[32768],   g_wqwBl[32768];     // wq_w as B: 16 x 32
__device__ uint32_t g_lo1Bh[131072],  g_lo1Bl[131072];    // lo_w[:, :512] as B: 64 x 32
__device__ uint32_t g_lo2Bh[131072],  g_lo2Bl[131072];    // lo_w[:, 512:] as B: 64 x 32
__device__ uint32_t g_attnAh[524288], g_attnAl[524288];   // attn as A: 64 x 64
__device__ uint32_t g_wcAh[262144],   g_wcAl[262144];     // wc as A: 64 x 32

#define TWO_LOG2E 2.8853900817779268f

__device__ __forceinline__ float fast_ex2(float x) {
    float e; asm("ex2.approx.f32 %0, %1;" : "=f"(e) : "f"(x)); return e;
}
__device__ __forceinline__ float fast_rcp(float x) {
    float r; asm("rcp.approx.f32 %0, %1;" : "=f"(r) : "f"(x)); return r;
}
__device__ __forceinline__ float fast_tanh(float x) {
    float e = fast_ex2(x * TWO_LOG2E);
    return fmaf(-2.0f, fast_rcp(e + 1.0f), 1.0f);
}

// ---------------- bf16 split helpers (validated R13/R14) ----------------
__device__ __forceinline__ uint32_t pack_hi(float e0, float e1) {
    uint32_t r;
    asm("prmt.b32 %0, %1, %2, 0x7632;" : "=r"(r)
        : "r"(__float_as_uint(e0)), "r"(__float_as_uint(e1)));
    return r;
}
__device__ __forceinline__ uint32_t pack_lo(float e0, float e1) {
    float h0 = __uint_as_float(__float_as_uint(e0) & 0xFFFF0000u);
    float h1 = __uint_as_float(__float_as_uint(e1) & 0xFFFF0000u);
    uint32_t r;
    asm("cvt.rn.bf16x2.f32 %0, %1, %2;" : "=r"(r) : "f"(e1 - h1), "f"(e0 - h0));
    return r;
}

__device__ __forceinline__ void mma_bf16(float* c, const uint32_t* a, const uint32_t* b) {
    asm volatile(
        "mma.sync.aligned.m16n8k16.row.col.f32.bf16.bf16.f32 "
        "{%0,%1,%2,%3}, {%4,%5,%6,%7}, {%8,%9}, {%0,%1,%2,%3};"
        : "+f"(c[0]), "+f"(c[1]), "+f"(c[2]), "+f"(c[3])
        : "r"(a[0]), "r"(a[1]), "r"(a[2]), "r"(a[3]), "r"(b[0]), "r"(b[1]));
}

// ---------------- conversion warp-tasks (validated R14) ----------------
__device__ __forceinline__ void conv_A(const float* __restrict__ X, int ld,
                                       int mt, int kt, int nkt,
                                       uint32_t* __restrict__ Ah,
                                       uint32_t* __restrict__ Al, int lane)
{
    const int g = lane >> 2, t4 = lane & 3;
    uint4 h, l;
    uint32_t* ph = &h.x; uint32_t* pl = &l.x;
#pragma unroll
    for (int j = 0; j < 4; j++) {
        const int r = mt * 16 + g + 8 * (j & 1);
        const int k = kt * 16 + t4 * 2 + 8 * (j >> 1);
        float2 v = *(const float2*)&X[(long)r * ld + k];
        ph[j] = pack_hi(v.x, v.y);
        pl[j] = pack_lo(v.x, v.y);
    }
    const long base = ((long)mt * nkt + kt) * 128 + lane * 4;
    *(uint4*)&Ah[base] = h;
    *(uint4*)&Al[base] = l;
}

__device__ __forceinline__ void conv_B_rm(const float* __restrict__ X, int ld,
                                          int ntb, int kt, int nkt,
                                          uint32_t* __restrict__ Bh,
                                          uint32_t* __restrict__ Bl, int lane)
{
    const int n = ntb * 8 + (lane >> 2), t4 = lane & 3;
    uint2 h, l;
#pragma unroll
    for (int j = 0; j < 2; j++) {
        const int k = kt * 16 + t4 * 2 + 8 * j;
        float2 v = *(const float2*)&X[(long)n * ld + k];
        (&h.x)[j] = pack_hi(v.x, v.y);
        (&l.x)[j] = pack_lo(v.x, v.y);
    }
    const long base = ((long)ntb * nkt + kt) * 64 + lane * 2;
    *(uint2*)&Bh[base] = h;
    *(uint2*)&Bl[base] = l;
}

__device__ __forceinline__ void conv_B_tr(const float* __restrict__ X, int ld,
                                          int ntb, int kt, int nkt,
                                          uint32_t* __restrict__ Bh,
                                          uint32_t* __restrict__ Bl, int lane)
{
    const int n = ntb * 8 + (lane >> 2), t4 = lane & 3;
    uint2 h, l;
#pragma unroll
    for (int j = 0; j < 2; j++) {
        const int k = kt * 16 + t4 * 2 + 8 * j;
        float x0 = X[(long)k * ld + n];
        float x1 = X[(long)(k + 1) * ld + n];
        (&h.x)[j] = pack_hi(x0, x1);
        (&l.x)[j] = pack_lo(x0, x1);
    }
    const long base = ((long)ntb * nkt + kt) * 64 + lane * 2;
    *(uint2*)&Bh[base] = h;
    *(uint2*)&Bl[base] = l;
}

// ---------------- input conversion kernel (7936 CTAs x 128) ----------------
__global__ __launch_bounds__(128)
void conv_inputs_kernel(const float* __restrict__ context,
                        const float* __restrict__ query,
                        const float* __restrict__ wc_w,
                        const float* __restrict__ wq_w,
                        const float* __restrict__ lo_w)
{
    const int task = blockIdx.x * 4 + (threadIdx.x >> 5);
    const int lane = threadIdx.x & 31;

    if (task < 8192) {
        conv_A(context, CDIM, task >> 5, task & 31, 32, g_ctxAh, g_ctxAl, lane);
    } else if (task < 10240) {
        const int t = task - 8192;
        conv_A(query, QDIM, t >> 5, t & 31, 32, g_qryAh, g_qryAl, lane);
    } else if (task < 26624) {
        const int t = task - 10240;
        const int b = t >> 12, rem = t & 4095;
        conv_B_tr(context + (long)b * CCN * CDIM, CDIM, rem >> 6, rem & 63, 64,
                  g_ctxBh + (long)b * 262144, g_ctxBl + (long)b * 262144, lane);
    } else if (task < 27136) {
        const int t = task - 26624;
        conv_B_rm(wc_w, CDIM, t >> 5, t & 31, 32, g_wcwBh, g_wcwBl, lane);
    } else if (task < 27648) {
        const int t = task - 27136;
        conv_B_rm(wq_w, QDIM, t >> 5, t & 31, 32, g_wqwBh, g_wqwBl, lane);
    } else if (task < 29696) {
        const int t = task - 27648;
        conv_B_rm(lo_w, QDIM + CDIM, t >> 5, t & 31, 32, g_lo1Bh, g_lo1Bl, lane);
    } else {
        const int t = task - 29696;
        conv_B_rm(lo_w + CDIM, QDIM + CDIM, t >> 5, t & 31, 32, g_lo2Bh, g_lo2Bl, lane);
    }
}

// ---------------- frag-staged tensor-core GEMM (validated R14/R15) ---------
__device__ __forceinline__
void gemm_fs(const uint32_t* __restrict__ Ah, const uint32_t* __restrict__ Al,
             int a_mt0, int a_nkt,
             const uint32_t* __restrict__ Bh, const uint32_t* __restrict__ Bl,
             int b_nt0, int b_nkt,
             const float* __restrict__ bias, const float* __restrict__ Add,
             float* __restrict__ C, int ldc, int m_base, int n0,
             int NKT, int epi,
             uint32_t* __restrict__ FAh, uint32_t* __restrict__ FAl,
             int f_mt0, int f_nkt)
{
    __shared__ uint32_t As[2048];
    __shared__ uint32_t Bs[2048];

    const int tid  = threadIdx.x;
    const int lane = tid & 31;
    const int wid  = tid >> 5;
    const int wm   = wid >> 2;
    const int wn   = wid & 3;

    const int gA = tid >> 5, mtA = gA & 3, spA = gA >> 2;
    const int ixA = (tid & 31) * 4;
    const int spB = tid >> 7, ntB = (tid >> 4) & 7;
    const int ixB = (tid & 15) * 4;

    const uint32_t* srcA = (spA ? Al : Ah) + ((long)(a_mt0 + mtA) * a_nkt) * 128 + ixA;
    const uint32_t* srcB = (spB ? Bl : Bh) + ((long)(b_nt0 + ntB) * b_nkt) * 64 + ixB;
    uint32_t* const dstA = &As[(spA * 4 + mtA) * 128 + ixA];
    uint32_t* const dstB = &Bs[(spB * 8 + ntB) * 64 + ixB];

    float acc[2][2][4];
#pragma unroll
    for (int mt = 0; mt < 2; mt++)
#pragma unroll
        for (int nt = 0; nt < 2; nt++)
#pragma unroll
            for (int i = 0; i < 4; i++) acc[mt][nt][i] = 0.f;

    uint4 ra = *(const uint4*)(srcA);
    uint4 rb = *(const uint4*)(srcB);
    *(uint4*)dstA = ra;
    *(uint4*)dstB = rb;
    if (1 < NKT) {
        ra = *(const uint4*)(srcA + 128);
        rb = *(const uint4*)(srcB + 64);
    }
    __syncthreads();

    int cur = 0;
    for (int kt = 0; kt < NKT; kt++) {
        uint32_t ah[2][4], al[2][4], bh[2][2], bl[2][2];
#pragma unroll
        for (int mt = 0; mt < 2; mt++) {
            const int mtile = wm * 2 + mt;
            *(uint4*)ah[mt] = *(const uint4*)&As[(cur * 8 + mtile) * 128 + lane * 4];
            *(uint4*)al[mt] = *(const uint4*)&As[(cur * 8 + 4 + mtile) * 128 + lane * 4];
        }
#pragma unroll
        for (int nt = 0; nt < 2; nt++) {
            const int ntile = wn * 2 + nt;
            *(uint2*)bh[nt] = *(const uint2*)&Bs[(cur * 16 + ntile) * 64 + lane * 2];
            *(uint2*)bl[nt] = *(const uint2*)&Bs[(cur * 16 + 8 + ntile) * 64 + lane * 2];
        }
#pragma unroll
        for (int mt = 0; mt < 2; mt++)
#pragma unroll
            for (int nt = 0; nt < 2; nt++) {
                mma_bf16(acc[mt][nt], ah[mt], bh[nt]);
                mma_bf16(acc[mt][nt], ah[mt], bl[nt]);
                mma_bf16(acc[mt][nt], al[mt], bh[nt]);
            }

        if (kt + 1 < NKT) {
            *(uint4*)(dstA + (cur ^ 1) * 1024) = ra;
            *(uint4*)(dstB + (cur ^ 1) * 1024) = rb;
        }
        if (kt + 2 < NKT) {
            ra = *(const uint4*)(srcA + (long)(kt + 2) * 128);
            rb = *(const uint4*)(srcB + (long)(kt + 2) * 64);
        }
        __syncthreads();
        cur ^= 1;
    }

    if (FAh) {
        const int ktg = (n0 >> 4) + wn;
#pragma unroll
        for (int mt = 0; mt < 2; mt++) {
            const int mtg = f_mt0 + wm * 2 + mt;
            uint4 h, l;
            h.x = pack_hi(acc[mt][0][0], acc[mt][0][1]);
            l.x = pack_lo(acc[mt][0][0], acc[mt][0][1]);
            h.y = pack_hi(acc[mt][0][2], acc[mt][0][3]);
            l.y = pack_lo(acc[mt][0][2], acc[mt][0][3]);
            h.z = pack_hi(acc[mt][1][0], acc[mt][1][1]);
            l.z = pack_lo(acc[mt][1][0], acc[mt][1][1]);
            h.w = pack_hi(acc[mt][1][2], acc[mt][1][3]);
            l.w = pack_lo(acc[mt][1][2], acc[mt][1][3]);
            const long base = ((long)mtg * f_nkt + ktg) * 128 + lane * 4;
            *(uint4*)&FAh[base] = h;
            *(uint4*)&FAl[base] = l;
        }
        return;
    }

    const int g   = lane >> 2;
    const int tig = lane & 3;
#pragma unroll
    for (int mt = 0; mt < 2; mt++)
#pragma unroll
        for (int nt = 0; nt < 2; nt++) {
            const int col = n0 + wn * 16 + nt * 8 + tig * 2;
            float2 b2 = bias ? *(const float2*)&bias[col] : make_float2(0.f, 0.f);
#pragma unroll
            for (int half = 0; half < 2; half++) {
                const int row = m_base + wm * 32 + mt * 16 + g + half * 8;
                float v0 = acc[mt][nt][half * 2 + 0] + b2.x;
                float v1 = acc[mt][nt][half * 2 + 1] + b2.y;
                if (Add) {
                    float2 a2 = *(const float2*)&Add[(long)row * ldc + col];
                    v0 += a2.x; v1 += a2.y;
                }
                if (epi == 1) {
                    v0 = fast_ex2(v0 * TWO_LOG2E); v1 = fast_ex2(v1 * TWO_LOG2E);
                } else if (epi == 2) {
                    v0 = fast_tanh(v0); v1 = fast_tanh(v1);
                }
                *(float2*)&C[(long)row * ldc + col] = make_float2(v0, v1);
            }
        }
}

// ---------------- fused projections: Ec, Eq, qpart (288 CTAs) --------------
__global__ __launch_bounds__(256)
void proj_fused_kernel(const float* __restrict__ wc_b,
                       const float* __restrict__ wq_b,
                       const float* __restrict__ lo_b,
                       float* __restrict__ Ec, float* __restrict__ Eq,
                       float* __restrict__ qpart)
{
    const int i = blockIdx.x;
    if (i < 128) {
        const int m0 = (i >> 1) * 64, n0 = (i & 1) * 64;
        gemm_fs(g_ctxAh, g_ctxAl, m0 >> 4, 32,
                g_wcwBh, g_wcwBl, n0 >> 3, 32,
                wc_b, nullptr, Ec, HH, m0, n0, 32, 1,
                nullptr, nullptr, 0, 0);
    } else if (i < 160) {
        const int j = i - 128;
        const int m0 = (j >> 1) * 64, n0 = (j & 1) * 64;
        gemm_fs(g_qryAh, g_qryAl, m0 >> 4, 32,
                g_wqwBh, g_wqwBl, n0 >> 3, 32,
                wq_b, nullptr, Eq, HH, m0, n0, 32, 1,
                nullptr, nullptr, 0, 0);
    } else {
        const int j = i - 160;
        const int m0 = (j >> 3) * 64, n0 = (j & 7) * 64;
        gemm_fs(g_qryAh, g_qryAl, m0 >> 4, 32,
                g_lo2Bh, g_lo2Bl, n0 >> 3, 32,
                lo_b, nullptr, qpart, QDIM, m0, n0, 32, 0,
                nullptr, nullptr, 0, 0);
    }
}

// ---------------- wc = attn @ context -> frag out (128 CTAs) ---------------
__global__ __launch_bounds__(256)
void gemm_nn_kernel()
{
    const int b  = blockIdx.z;
    const int m0 = blockIdx.y * 64;
    const int n0 = blockIdx.x * 64;
    const int mt0 = (b * QQ + m0) >> 4;
    gemm_fs(g_attnAh, g_attnAl, mt0, 64,
            g_ctxBh + (long)b * 262144, g_ctxBl + (long)b * 262144, n0 >> 3, 64,
            nullptr, nullptr, nullptr, 0, 0, n0, 64, 0,
            g_wcAh, g_wcAl, mt0, 32);
}

// ---------------- out = tanh(wc @ lo_w[:,:512].T + qpart) (128 CTAs) -------
__global__ __launch_bounds__(256)
void gemm_out_kernel(const float* __restrict__ qpart, float* __restrict__ out)
{
    const int m0 = blockIdx.y * 64, n0 = blockIdx.x * 64;
    gemm_fs(g_wcAh, g_wcAl, m0 >> 4, 32,
            g_lo1Bh, g_lo1Bl, n0 >> 3, 32,
            nullptr, qpart, out, QDIM, m0, n0, 32, 2,
            nullptr, nullptr, 0, 0);
}

// ---------------- emission + softmax + inline attn frag conversion ---------
// Paired reciprocals (R15). After softmax, the CTA stages its QT=4 rows of
// attn in smem and emits their A-frag u32s directly (each frag u32 holds 2
// k-values of exactly ONE row -> rows partition the frag arrays; no races).
#define QT 4
#define CH 32
#define NCHUNK (CCN / CH)
#define ECPAD 132

__global__ __launch_bounds__(128)
void emission_softmax2(const float* __restrict__ Ec,
                       const float* __restrict__ Eq,
                       const int* __restrict__ mask,
                       const float* __restrict__ we_w,
                       const float* __restrict__ we_b,
                       float* __restrict__ attn)
{
    __shared__ float ecs[CH][ECPAD];
    __shared__ float eqs[QT][HH];
    __shared__ float wes[HH];
    __shared__ int ms[CH];
    __shared__ float att_s[QT][CCN];   // 16KB

    const int b  = blockIdx.y;
    const int q0 = blockIdx.x * QT;
    const int tid = threadIdx.x;
    const int lane = tid & 31;
    const int q = tid >> 5;

    if (tid < HH) wes[tid] = we_w[tid];
    {
        const float4* src = (const float4*)&Eq[(long)(b * QQ + q0) * HH];
        float4* dst = (float4*)&eqs[0][0];
        for (int i = tid; i < QT * HH / 4; i += 128) dst[i] = src[i];
    }
    __syncthreads();

    float W = 0.f;
#pragma unroll
    for (int h = 0; h < HH; h += 4) {
        float4 w4 = *(const float4*)&wes[h];
        W += (w4.x + w4.y) + (w4.z + w4.w);
    }
    const float eb = we_b[0];

    float es_l[NCHUNK];

    for (int ch = 0; ch < NCHUNK; ch++) {
        __syncthreads();
        {
            const float4* src = (const float4*)&Ec[((long)b * CCN + ch * CH) * HH];
            for (int i = tid; i < CH * HH / 4; i += 128) {
                int r  = i >> 5;
                int c4 = (i & 31) * 4;
                *(float4*)&ecs[r][c4] = src[i];
            }
            if (tid < CH) ms[tid] = mask[b * CCN + ch * CH + tid];
        }
        __syncthreads();

        float s0 = 0.f, s1 = 0.f;
#pragma unroll
        for (int h = 0; h < HH; h += 8) {
            float4 e0 = *(const float4*)&ecs[lane][h];
            float4 g0 = *(const float4*)&eqs[q][h];
            float4 w0 = *(const float4*)&wes[h];
            float4 e1 = *(const float4*)&ecs[lane][h + 4];
            float4 g1 = *(const float4*)&eqs[q][h + 4];
            float4 w1 = *(const float4*)&wes[h + 4];

            {
                float A0 = fmaf(e0.x, g0.x, 1.f), A1 = fmaf(e0.y, g0.y, 1.f);
                float num = fmaf(w0.x, A1, w0.y * A0);
                s0 = fmaf(num, fast_rcp(A0 * A1), s0);
            }
            {
                float A0 = fmaf(e0.z, g0.z, 1.f), A1 = fmaf(e0.w, g0.w, 1.f);
                float num = fmaf(w0.z, A1, w0.w * A0);
                s1 = fmaf(num, fast_rcp(A0 * A1), s1);
            }
            {
                float A0 = fmaf(e1.x, g1.x, 1.f), A1 = fmaf(e1.y, g1.y, 1.f);
                float num = fmaf(w1.x, A1, w1.y * A0);
                s0 = fmaf(num, fast_rcp(A0 * A1), s0);
            }
            {
                float A0 = fmaf(e1.z, g1.z, 1.f), A1 = fmaf(e1.w, g1.w, 1.f);
                float num = fmaf(w1.z, A1, w1.w * A0);
                s1 = fmaf(num, fast_rcp(A0 * A1), s1);
            }
        }
        float s = s0 + s1;
        es_l[ch] = ms[lane] ? (fmaf(-2.f, s, W) + eb) : -INFINITY;
    }

    float lm = -INFINITY;
#pragma unroll
    for (int ch = 0; ch < NCHUNK; ch++) lm = fmaxf(lm, es_l[ch]);
#pragma unroll
    for (int off = 16; off >= 1; off >>= 1)
        lm = fmaxf(lm, __shfl_xor_sync(0xffffffffu, lm, off));
    const bool ok = (lm > -3.0e38f);

    float ls = 0.f;
#pragma unroll
    for (int ch = 0; ch < NCHUNK; ch++) {
        float e = ok ? __expf(es_l[ch] - lm) : 0.f;
        es_l[ch] = e;
        ls += e;
    }
#pragma unroll
    for (int off = 16; off >= 1; off >>= 1)
        ls += __shfl_xor_sync(0xffffffffu, ls, off);
    const float inv = (ls > 0.f) ? 1.f / ls : 0.f;

    float* arow = attn + (long)(b * QQ + q0 + q) * CCN;
#pragma unroll
    for (int ch = 0; ch < NCHUNK; ch++) {
        float v = es_l[ch] * inv;
        arow[ch * CH + lane] = v;
        att_s[q][ch * CH + lane] = v;
    }
    __syncthreads();

    // ---- inline attn -> A-frag (hi/lo) for this CTA's 4 rows ----
    // 2048 u32-pairs: rr(4) x kt(64) x t4(4) x khalf(2)
    for (int t = tid; t < 2048; t += 128) {
        const int rr    = t >> 9;
        const int rem   = t & 511;
        const int kt    = rem >> 3;
        const int t4    = (rem >> 1) & 3;
        const int khalf = rem & 1;
        const int m     = b * QQ + q0 + rr;
        const int mt    = m >> 4, rsub = m & 15;
        const int l     = (rsub & 7) * 4 + t4;
        const int j     = (rsub >> 3) + 2 * khalf;
        const int k     = kt * 16 + t4 * 2 + 8 * khalf;
        float2 v = *(const float2*)&att_s[rr][k];
        const long base = ((long)mt * 64 + kt) * 128 + l * 4 + j;
        g_attnAh[base] = pack_hi(v.x, v.y);
        g_attnAl[base] = pack_lo(v.x, v.y);
    }
}

// ---------------- launcher: serial single-stream (graph-safe) --------------
extern "C" void kernel_launch(void* const* d_in, const int* in_sizes, int n_in,
                              void* d_out, int out_size)
{
    const float* query   = (const float*)d_in[0];
    const float* context = (const float*)d_in[1];
    const int*   mask    = (const int*)d_in[2];
    const float* wq_w = (const float*)d_in[3];
    const float* wq_b = (const float*)d_in[4];
    const float* wc_w = (const float*)d_in[5];
    const float* wc_b = (const float*)d_in[6];
    const float* we_w = (const float*)d_in[7];
    const float* we_b = (const float*)d_in[8];
    const float* lo_w = (const float*)d_in[9];
    const float* lo_b = (const float*)d_in[10];

    float *Ec, *Eq, *qpart, *attn_s;
    cudaGetSymbolAddress((void**)&Ec, g_Ec);
    cudaGetSymbolAddress((void**)&Eq, g_Eq);
    cudaGetSymbolAddress((void**)&qpart, g_qpart);
    cudaGetSymbolAddress((void**)&attn_s, g_attn_scratch);

    const int nOut  = BB * QQ * QDIM;
    const int nAttn = BB * QQ * CCN;
    float* outPtr  = nullptr;
    float* attnPtr = nullptr;
    if (out_size >= nOut + nAttn) {
        outPtr  = (float*)d_out;
        attnPtr = (float*)d_out + nOut;
    } else if (out_size == nAttn) {
        attnPtr = (float*)d_out;
    } else {
        outPtr = (float*)d_out;
    }
    if (!attnPtr) attnPtr = attn_s;

    // 1) convert all GEMM inputs to fragment-blocked bf16 hi/lo
    conv_inputs_kernel<<<7936, 128>>>(context, query, wc_w, wq_w, lo_w);

    // 2) Ec, Eq, qpart (tensor cores, 288 CTAs)
    proj_fused_kernel<<<288, 256>>>(wc_b, wq_b, lo_b, Ec, Eq, qpart);

    // 3) emission + softmax -> attn (fp32 out + inline frag conversion)
    emission_softmax2<<<dim3(QQ / QT, BB), 128>>>(Ec, Eq, mask, we_w, we_b, attnPtr);

    if (outPtr) {
        // 4) wc = attn @ context, written directly as A-frags (128 CTAs)
        gemm_nn_kernel<<<dim3(CDIM / 64, QQ / 64, BB), 256>>>();

        // 5) out = tanh(wc @ lo_w[:,:512].T + qpart) (128 CTAs)
        gemm_out_kernel<<<dim3(QDIM / 64, BB * QQ / 64), 256>>>(qpart, outPtr);
    }
}